// round 15
// baseline (speedup 1.0000x reference)
#include <cuda_runtime.h>
#include <math.h>
#include <stdint.h>

#define R_N 1000
#define K_N 80
#define NCLS_P1 81
#define IMG_W_F 1333.0f
#define IMG_H_F 800.0f
#define CPC 100
#define OUT_COLS 87
#define TB 1024
#define SURV_CAP 512

typedef unsigned long long u64;
typedef unsigned int u32;

__device__ u64 g_isum = 0;                 // fixed-point sum (x 2^32)
__device__ u32 g_imax = 0;                 // ord32 of global fg max
__device__ u64 g_keys[K_N * CPC];          // compacted kept keys
__device__ int g_props[K_N * CPC];         // matching proposal rows
__device__ u32 g_hist[256];                // top-byte histogram (built at emit)
__device__ int g_total = 0;
__device__ int g_bar1 = 0;
__device__ int g_bar2 = 0;

__device__ __forceinline__ u32 ord32(float f) {
    u32 u = __float_as_uint(f);
    return (u & 0x80000000u) ? ~u : (u | 0x80000000u);
}

// ---- dynamic smem: per-class layout (identical to the 23.3us R12 kernel) ----
#define OFF_CSCORE 0        // float[1024]
#define OFF_CIDX   4096     // int[1024]
#define OFF_CAREA  8192     // float[1024]
#define OFF_CBX    12288    // float4[1024] -> 28672
#define OFF_SSCORE 28672    // float[1024]
#define OFF_SIDX   32768    // int[1024]
#define OFF_SAREA  36864    // float[1024]
#define OFF_SBX    40960    // float4[1024] -> 57344
#define OFF_ADJ    57344    // u32[512]     -> 59392
#define OFF_KEEP   0        // int[1024] fallback overlay (cscore region; dead then)
// ---- tail layout (last block; per-class data dead) ----
#define OFF_HIST   0        // u32[256]
#define OFF_SURV   1024     // u64[512]
#define OFF_SPROP  5120     // int[512]
#define OFF_WIN    7168     // u64[128]
#define OFF_WPROP  8192     // int[128]  -> 8704
#define DYN_SMEM   59392

__global__ void __launch_bounds__(TB) fused_kernel(const float* __restrict__ boxes,
                                                   const float* __restrict__ scores,
                                                   float* __restrict__ out) {
    extern __shared__ char smraw[];
    float*  cscore = (float*)(smraw + OFF_CSCORE);
    int*    cidx   = (int*)(smraw + OFF_CIDX);
    float*  carea  = (float*)(smraw + OFF_CAREA);
    float4* cbx    = (float4*)(smraw + OFF_CBX);
    float*  sscore = (float*)(smraw + OFF_SSCORE);
    int*    sidx   = (int*)(smraw + OFF_SIDX);
    float*  sarea  = (float*)(smraw + OFF_SAREA);
    float4* sbx    = (float4*)(smraw + OFF_SBX);
    u32*    adjw   = (u32*)(smraw + OFF_ADJ);
    int*    s_keep = (int*)(smraw + OFF_KEEP);

    __shared__ float wsum[TB / 32], wmax[TB / 32];
    __shared__ int klist[CPC];
    __shared__ float s_th;
    __shared__ int s_cnt, s_nk, s_chosen, s_need, s_scount, s_n;
    __shared__ int s_last, s_spred;

    int t = threadIdx.x;
    int b = blockIdx.x;       // class id

    // ==== Phase 1: load + reduce + SPECULATIVE compact (valid-only gather) ===
    if (t == 0) s_cnt = 0;
    __syncthreads();                                   // B1
    {
        float psum = 0.f, pmax = -INFINITY;
        for (int r = t; r < R_N; r += TB) {
            float v = __ldg(scores + r * NCLS_P1 + b);
            psum += v;
            pmax = fmaxf(pmax, v);
            if (v > 0.05f) {                           // speculation: th == 0.05f
                int p = atomicAdd(&s_cnt, 1);
                cscore[p] = v;
                cidx[p] = r;
                float4 bx = __ldg((const float4*)boxes + r * K_N + b);
                float x1 = fminf(fmaxf(bx.x, 0.f), IMG_W_F);
                float y1 = fminf(fmaxf(bx.y, 0.f), IMG_H_F);
                float x2 = fminf(fmaxf(bx.z, 0.f), IMG_W_F);
                float y2 = fminf(fmaxf(bx.w, 0.f), IMG_H_F);
                cbx[p] = make_float4(x1, y1, x2, y2);
                carea[p] = fmaxf(x2 - x1, 0.f) * fmaxf(y2 - y1, 0.f);
            }
        }
        for (int w = t; w < 512; w += TB) adjw[w] = 0;  // zero adjacency now
        #pragma unroll
        for (int o = 16; o; o >>= 1) {
            psum += __shfl_xor_sync(0xffffffffu, psum, o);
            pmax = fmaxf(pmax, __shfl_xor_sync(0xffffffffu, pmax, o));
        }
        if ((t & 31) == 0) { wsum[t >> 5] = psum; wmax[t >> 5] = pmax; }
    }
    __syncthreads();                                   // B2

    float th_cur = 0.05f;
    int V = 0;
    for (int attempt = 0; ; attempt++) {
        V = s_cnt;

        // warp 31 (attempt 0): fold partials + global atomics + bar1 arrive
        if (attempt == 0 && t >= TB - 32) {
            int lane = t & 31;
            float s = wsum[lane], m = wmax[lane];
            #pragma unroll
            for (int o = 16; o; o >>= 1) {
                s += __shfl_xor_sync(0xffffffffu, s, o);
                m = fmaxf(m, __shfl_xor_sync(0xffffffffu, m, o));
            }
            if (lane == 0) {
                atomicAdd(&g_isum, (u64)(s * 4294967296.0f));
                atomicMax(&g_imax, ord32(m));
                __threadfence();
                atomicAdd(&g_bar1, 1);
            }
        }

        // rank-counting sort (score desc, idx asc): pure smem permutation
        for (int i = t; i < V; i += TB) {
            float si = cscore[i];
            int   ii = cidx[i];
            int rank = 0;
            for (int j = 0; j < V; j++) {
                float sj = cscore[j];
                rank += (sj > si) || (sj == si && cidx[j] < ii);
            }
            sscore[rank] = si;
            sidx[rank]   = ii;
            sbx[rank]    = cbx[i];
            sarea[rank]  = carea[i];
        }
        __syncthreads();                               // B3

        // thread 1023: verify-spin overlapped with adjacency build (attempt 0)
        if (attempt == 0 && t == TB - 1) {
            while (*(volatile int*)&g_bar1 < K_N) { }
            __threadfence();
            u64 isum = *(volatile u64*)&g_isum;
            u32 imax = *(volatile u32*)&g_imax;
            float mean = (float)isum * (1.0f / 4294967296.0f) / (float)(R_N * K_N);
            float mx = __uint_as_float(imax & 0x7FFFFFFFu);   // scores >= 0
            s_th = fminf(0.05f, 0.5f * (mean + mx));
        }

        // adjacency build on SORTED indices (upper triangle), V <= 128 path
        if (V <= 128) {
            int tot = V * V;
            if (t < TB - 32) {
                for (int p = t; p < tot; p += TB - 32) {
                    int i = p / V, j = p - i * V;
                    if (j > i) {
                        float4 bi = sbx[i], bj = sbx[j];
                        float xx1 = fmaxf(bi.x, bj.x);
                        float yy1 = fmaxf(bi.y, bj.y);
                        float xx2 = fminf(bi.z, bj.z);
                        float yy2 = fminf(bi.w, bj.w);
                        float inter = fmaxf(xx2 - xx1, 0.f) * fmaxf(yy2 - yy1, 0.f);
                        float uni = fmaxf(sarea[i] + sarea[j] - inter, 1e-9f);
                        if (inter > 0.5f * uni)
                            atomicOr(&adjw[i * 4 + (j >> 5)], 1u << (j & 31));
                    }
                }
            }
        }
        __syncthreads();                               // B4

        if (attempt == 0 && s_th != th_cur) {
            // rare: redo with the true threshold (reload from global)
            th_cur = s_th;
            if (t == 0) s_cnt = 0;
            __syncthreads();
            for (int r = t; r < R_N; r += TB) {
                float v = __ldg(scores + r * NCLS_P1 + b);
                if (v > th_cur) {
                    int p = atomicAdd(&s_cnt, 1);
                    cscore[p] = v;
                    cidx[p] = r;
                    float4 bx = __ldg((const float4*)boxes + r * K_N + b);
                    float x1 = fminf(fmaxf(bx.x, 0.f), IMG_W_F);
                    float y1 = fminf(fmaxf(bx.y, 0.f), IMG_H_F);
                    float x2 = fminf(fmaxf(bx.z, 0.f), IMG_W_F);
                    float y2 = fminf(fmaxf(bx.w, 0.f), IMG_H_F);
                    cbx[p] = make_float4(x1, y1, x2, y2);
                    carea[p] = fmaxf(x2 - x1, 0.f) * fmaxf(y2 - y1, 0.f);
                }
            }
            for (int w = t; w < 512; w += TB) adjw[w] = 0;
            __syncthreads();
            continue;
        }
        break;
    }

    // ==== Closure + emit + bar2 arrive: all in warp 0, no extra barriers ====
    if (V <= 128) {
        if (t < 32) {
            if (t == 0) {          // pipelined closure over sorted rows -> klist
                u64 a0 = (V >= 64) ? ~0ull : ((1ull << V) - 1ull);
                u64 a1 = (V <= 64) ? 0ull : ((V >= 128) ? ~0ull : ((1ull << (V - 64)) - 1ull));
                u64 n0 = 0, n1 = 0;
                if (V > 0) {
                    n0 = ((u64)adjw[1] << 32) | adjw[0];
                    n1 = ((u64)adjw[3] << 32) | adjw[2];
                }
                int nk = 0;
                for (int i = 0; i < V; i++) {
                    u64 c0 = n0, c1 = n1;
                    if (i + 1 < V) {           // prefetch next row
                        n0 = ((u64)adjw[(i + 1) * 4 + 1] << 32) | adjw[(i + 1) * 4 + 0];
                        n1 = ((u64)adjw[(i + 1) * 4 + 3] << 32) | adjw[(i + 1) * 4 + 2];
                    }
                    u64 w = (i < 64) ? a0 : a1;
                    if ((w >> (i & 63)) & 1ull) {
                        klist[nk++] = i;
                        if (nk >= CPC) break;
                        a0 &= ~c0; a1 &= ~c1;
                    }
                }
                s_nk = nk;
            }
            __syncwarp();
            int nk = s_nk;
            int base = 0;
            if (t == 0) base = atomicAdd(&g_total, nk);
            base = __shfl_sync(0xffffffffu, base, 0);
            for (int k = t; k < nk; k += 32) {
                int i = klist[k];
                u32 o = ord32(sscore[i]);
                // low-32 strictly decreasing in flat (c,k) => ties break like top_k
                u64 key = ((u64)o << 32) | (u32)(((K_N - 1 - b) << 7) | (CPC - 1 - k));
                g_keys[base + k]  = key;
                g_props[base + k] = sidx[i];
                atomicAdd(&g_hist[o >> 24], 1u);
            }
            __syncwarp();
            if (t == 0) {
                __threadfence();
                int old = atomicAdd(&g_bar2, 1);
                s_last = (old == K_N - 1);
                if (s_last) {
                    __threadfence();
                    s_n = *(volatile int*)&g_total;
                    s_scount = 0;
                }
            }
        }
    } else {
        // generic fallback: serial block NMS on sorted arrays (rare)
        for (int i = t; i < V; i += TB) s_keep[i] = 1;
        __syncthreads();
        for (int i = 0; i < V; i++) {
            if (s_keep[i]) {
                float4 bi = sbx[i];
                float  ai = sarea[i];
                for (int j = i + 1 + t; j < V; j += TB) {
                    if (s_keep[j]) {
                        float4 bj = sbx[j];
                        float xx1 = fmaxf(bi.x, bj.x);
                        float yy1 = fmaxf(bi.y, bj.y);
                        float xx2 = fminf(bi.z, bj.z);
                        float yy2 = fminf(bi.w, bj.w);
                        float inter = fmaxf(xx2 - xx1, 0.f) * fmaxf(yy2 - yy1, 0.f);
                        float uni = fmaxf(ai + sarea[j] - inter, 1e-9f);
                        if (inter > 0.5f * uni) s_keep[j] = 0;
                    }
                }
            }
            __syncthreads();
        }
        if (t == 0) {
            int nk = 0;
            for (int i = 0; i < V && nk < CPC; i++)
                if (s_keep[i]) klist[nk++] = i;
            s_nk = nk;
        }
        __syncthreads();
        if (t < 32) {
            int nk = s_nk;
            int base = 0;
            if (t == 0) base = atomicAdd(&g_total, nk);
            base = __shfl_sync(0xffffffffu, base, 0);
            for (int k = t; k < nk; k += 32) {
                int i = klist[k];
                u32 o = ord32(sscore[i]);
                u64 key = ((u64)o << 32) | (u32)(((K_N - 1 - b) << 7) | (CPC - 1 - k));
                g_keys[base + k]  = key;
                g_props[base + k] = sidx[i];
                atomicAdd(&g_hist[o >> 24], 1u);
            }
            __syncwarp();
            if (t == 0) {
                __threadfence();
                int old = atomicAdd(&g_bar2, 1);
                s_last = (old == K_N - 1);
                if (s_last) {
                    __threadfence();
                    s_n = *(volatile int*)&g_total;
                    s_scount = 0;
                }
            }
        }
    }
    __syncthreads();                                   // B5 (publishes s_last)
    if (!s_last) return;
    int n = s_n;

    // ================= Tail: global top-100 ==================================
    u32* hist  = (u32*)(smraw + OFF_HIST);
    u64* surv  = (u64*)(smraw + OFF_SURV);
    int* sprop = (int*)(smraw + OFF_SPROP);
    u64* win   = (u64*)(smraw + OFF_WIN);
    int* wprop = (int*)(smraw + OFF_WPROP);

    if (t < 256) hist[t] = __ldcg(&g_hist[t]);
    if (t < 128) { win[t] = 0; wprop[t] = 0; }
    __syncthreads();

    u64 pref = 0;
    if (n > CPC) {
        // fast path: select top-byte bucket from the prebuilt histogram
        if (t < 32) {
            int lane = t;
            u32 h8[8]; int local = 0;
            #pragma unroll
            for (int q = 0; q < 8; q++) { h8[q] = hist[255 - 8 * lane - q]; local += (int)h8[q]; }
            int inc = local;
            #pragma unroll
            for (int o = 1; o < 32; o <<= 1) {
                int v2 = __shfl_up_sync(0xffffffffu, inc, o);
                if (lane >= o) inc += v2;
            }
            int pre = inc - local;
            if (pre < CPC && CPC <= inc) {
                int acc = pre;
                #pragma unroll
                for (int q = 0; q < 8; q++) {
                    int h = (int)h8[q];
                    if (acc + h >= CPC) {
                        s_chosen = 255 - 8 * lane - q;
                        s_spred = acc + h;
                        break;
                    }
                    acc += h;
                }
            }
        }
        __syncthreads();
        if (s_spred <= SURV_CAP) {
            pref = ((u64)(u32)s_chosen) << 56;
        } else {
            // exact fallback: full byte-radix over g_keys (rare, tie-heavy)
            u64 mask = 0;
            int need = CPC;
            int done = 0;
            pref = 0;
            #pragma unroll 1
            for (int pass = 0; pass < 8 && !done; pass++) {
                int shift = 8 * (7 - pass);
                if (t < 256) hist[t] = 0;
                __syncthreads();
                for (int i = t; i < n; i += TB) {
                    u64 kk = __ldcg(&g_keys[i]);
                    if ((kk & mask) == pref)
                        atomicAdd(&hist[(u32)(kk >> shift) & 255u], 1u);
                }
                __syncthreads();
                if (t < 32) {
                    int lane = t;
                    u32 h8[8]; int local = 0;
                    #pragma unroll
                    for (int q = 0; q < 8; q++) { h8[q] = hist[255 - 8 * lane - q]; local += (int)h8[q]; }
                    int inc = local;
                    #pragma unroll
                    for (int o = 1; o < 32; o <<= 1) {
                        int v2 = __shfl_up_sync(0xffffffffu, inc, o);
                        if (lane >= o) inc += v2;
                    }
                    int pre = inc - local;
                    if (pre < need && need <= inc) {
                        int acc = pre;
                        #pragma unroll
                        for (int q = 0; q < 8; q++) {
                            int h = (int)h8[q];
                            if (acc + h >= need) { s_chosen = 255 - 8 * lane - q; s_need = need - acc; break; }
                            acc += h;
                        }
                    }
                }
                __syncthreads();
                if (t == 0) s_spred = (CPC - s_need) + (int)hist[s_chosen];
                pref |= ((u64)(u32)s_chosen) << shift;
                mask |= 255ull << shift;
                need = s_need;
                __syncthreads();
                if (s_spred <= SURV_CAP) done = 1;
            }
        }
    }

    // gather survivors (key >= pref; pref==0 when n<=CPC => all)
    for (int i = t; i < n; i += TB) {
        u64 kk = __ldcg(&g_keys[i]);
        if (kk >= pref) {
            int p = atomicAdd(&s_scount, 1);
            if (p < SURV_CAP) { surv[p] = kk; sprop[p] = __ldcg(&g_props[i]); }
        }
    }
    __syncthreads();
    int S = s_scount;
    if (S > SURV_CAP) S = SURV_CAP;

    // rank survivors by full key (unique); keep top 100
    if (t < S) {
        u64 kk = surv[t];
        int r = 0;
        for (int j = 0; j < S; j++) r += (surv[j] > kk);
        if (r < CPC) { win[r] = kk; wprop[r] = sprop[t]; }
    }
    __syncthreads();

    // ---- Output: [100, 87] = box(4) | score | class | full_scores(81) ----
    for (int e = t; e < CPC * OUT_COLS; e += TB) {
        int row = e / OUT_COLS;
        int col = e - row * OUT_COLS;
        u64 key = win[row];
        u32 o = (u32)(key >> 32);
        float val = 0.f;
        if (o != 0u) {
            int c = (K_N - 1) - (int)(((u32)key >> 7) & 127u);
            int prop = wprop[row];
            if (col < 4) {
                float bv = __ldg(boxes + prop * (K_N * 4) + c * 4 + col);
                float lim = (col & 1) ? IMG_H_F : IMG_W_F;
                val = fminf(fmaxf(bv, 0.f), lim);
            } else if (col == 4) {
                val = __uint_as_float(o & 0x7FFFFFFFu);
            } else if (col == 5) {
                val = (float)c;
            } else {
                val = __ldg(scores + prop * NCLS_P1 + (col - 6));
            }
        }
        out[e] = val;
    }
    __syncthreads();
    // reset globals for next graph replay
    if (t < 256) g_hist[t] = 0;
    if (t == 0) {
        g_bar1 = 0; g_bar2 = 0; g_total = 0;
        g_isum = 0; g_imax = 0;
    }
}

// ---------------------------------------------------------------------------
extern "C" void kernel_launch(void* const* d_in, const int* in_sizes, int n_in,
                              void* d_out, int out_size) {
    const float* boxes  = (const float*)d_in[0];
    const float* scores = (const float*)d_in[1];
    if (in_sizes[0] != R_N * K_N * 4) {
        boxes  = (const float*)d_in[1];
        scores = (const float*)d_in[0];
    }
    cudaFuncSetAttribute(fused_kernel, cudaFuncAttributeMaxDynamicSharedMemorySize, DYN_SMEM);
    fused_kernel<<<K_N, TB, DYN_SMEM>>>(boxes, scores, (float*)d_out);
}

// round 16
// speedup vs baseline: 1.2476x; 1.2476x over previous
#include <cuda_runtime.h>
#include <math.h>
#include <stdint.h>

#define R_N 1000
#define K_N 80
#define NCLS_P1 81
#define IMG_W_F 1333.0f
#define IMG_H_F 800.0f
#define CPC 100
#define OUT_COLS 87
#define TB 1024
#define SURV_CAP 512

typedef unsigned long long u64;
typedef unsigned int u32;

__device__ u64 g_isum = 0;                 // fixed-point sum (x 2^32)
__device__ u32 g_imax = 0;                 // ord32 of global fg max
__device__ u64 g_keys[K_N * CPC];          // compacted kept keys
__device__ int g_props[K_N * CPC];         // matching proposal rows
__device__ u32 g_hist[256];                // top-byte histogram (built at emit)
__device__ int g_total = 0;
__device__ int g_bar1 = 0;
__device__ int g_bar2 = 0;

__device__ __forceinline__ u32 ord32(float f) {
    u32 u = __float_as_uint(f);
    return (u & 0x80000000u) ? ~u : (u | 0x80000000u);
}

// ---- dynamic smem: per-class layout ----
#define OFF_CSCORE 0        // float[1024]
#define OFF_CIDX   4096     // int[1024]
#define OFF_CAREA  8192     // float[1024]
#define OFF_CBX    12288    // float4[1024] -> 28672
#define OFF_SSCORE 28672    // float[1024]
#define OFF_SIDX   32768    // int[1024]
#define OFF_SAREA  36864    // float[1024]
#define OFF_SBX    40960    // float4[1024] -> 57344
#define OFF_ADJ    57344    // u32[512]     -> 59392
#define OFF_KEEP   0        // int[1024] fallback overlay (cscore region; dead then)
// ---- tail layout (last block; per-class data dead) ----
#define OFF_HIST   0        // u32[256]
#define OFF_SURV   1024     // u64[512]
#define OFF_SPROP  5120     // int[512]
#define OFF_WIN    7168     // u64[128]
#define OFF_WPROP  8192     // int[128]  -> 8704
#define DYN_SMEM   59392

__global__ void __launch_bounds__(TB) fused_kernel(const float* __restrict__ boxes,
                                                   const float* __restrict__ scores,
                                                   float* __restrict__ out) {
    extern __shared__ char smraw[];
    float*  cscore = (float*)(smraw + OFF_CSCORE);
    int*    cidx   = (int*)(smraw + OFF_CIDX);
    float*  carea  = (float*)(smraw + OFF_CAREA);
    float4* cbx    = (float4*)(smraw + OFF_CBX);
    float*  sscore = (float*)(smraw + OFF_SSCORE);
    int*    sidx   = (int*)(smraw + OFF_SIDX);
    float*  sarea  = (float*)(smraw + OFF_SAREA);
    float4* sbx    = (float4*)(smraw + OFF_SBX);
    u32*    adjw   = (u32*)(smraw + OFF_ADJ);
    int*    s_keep = (int*)(smraw + OFF_KEEP);

    __shared__ float wsum[TB / 32], wmax[TB / 32];
    __shared__ u32 keepw[32];
    __shared__ int klist[CPC];
    __shared__ float s_th;
    __shared__ int s_cnt, s_nk, s_chosen, s_need, s_scount, s_n;
    __shared__ int s_last, s_spred;

    int t = threadIdx.x;
    int b = blockIdx.x;       // class id

    // ==== Phase 1: load + reduce + SPECULATIVE compact (incl. box gather) ====
    if (t == 0) s_cnt = 0;
    __syncthreads();                                   // B1
    {
        float psum = 0.f, pmax = -INFINITY;
        for (int r = t; r < R_N; r += TB) {
            float v = __ldg(scores + r * NCLS_P1 + b);
            psum += v;
            pmax = fmaxf(pmax, v);
            if (v > 0.05f) {                           // speculation: th == 0.05f
                int p = atomicAdd(&s_cnt, 1);
                cscore[p] = v;
                cidx[p] = r;
                float4 bx = __ldg((const float4*)boxes + r * K_N + b);
                float x1 = fminf(fmaxf(bx.x, 0.f), IMG_W_F);
                float y1 = fminf(fmaxf(bx.y, 0.f), IMG_H_F);
                float x2 = fminf(fmaxf(bx.z, 0.f), IMG_W_F);
                float y2 = fminf(fmaxf(bx.w, 0.f), IMG_H_F);
                cbx[p] = make_float4(x1, y1, x2, y2);
                carea[p] = fmaxf(x2 - x1, 0.f) * fmaxf(y2 - y1, 0.f);
            }
        }
        for (int w = t; w < 512; w += TB) adjw[w] = 0;  // zero adjacency now
        #pragma unroll
        for (int o = 16; o; o >>= 1) {
            psum += __shfl_xor_sync(0xffffffffu, psum, o);
            pmax = fmaxf(pmax, __shfl_xor_sync(0xffffffffu, pmax, o));
        }
        if ((t & 31) == 0) { wsum[t >> 5] = psum; wmax[t >> 5] = pmax; }
    }
    __syncthreads();                                   // B2

    float th_cur = 0.05f;
    int V = 0;
    for (int attempt = 0; ; attempt++) {
        V = s_cnt;

        // warp 31: fold partials + global atomics + bar1 arrive (overlaps sort)
        if (attempt == 0 && t >= TB - 32) {
            int lane = t & 31;
            float s = wsum[lane], m = wmax[lane];
            #pragma unroll
            for (int o = 16; o; o >>= 1) {
                s += __shfl_xor_sync(0xffffffffu, s, o);
                m = fmaxf(m, __shfl_xor_sync(0xffffffffu, m, o));
            }
            if (lane == 0) {
                atomicAdd(&g_isum, (u64)(s * 4294967296.0f));
                atomicMax(&g_imax, ord32(m));
                __threadfence();
                atomicAdd(&g_bar1, 1);
            }
        }

        // rank-counting sort (score desc, idx asc): pure smem permutation
        for (int i = t; i < V; i += TB) {
            float si = cscore[i];
            int   ii = cidx[i];
            int rank = 0;
            for (int j = 0; j < V; j++) {
                float sj = cscore[j];
                rank += (sj > si) || (sj == si && cidx[j] < ii);
            }
            sscore[rank] = si;
            sidx[rank]   = ii;
            sbx[rank]    = cbx[i];
            sarea[rank]  = carea[i];
        }
        __syncthreads();                               // B3

        // thread 1023: verify-spin overlapped with NMS work (attempt 0)
        if (attempt == 0 && t == TB - 1) {
            while (*(volatile int*)&g_bar1 < K_N) { }
            __threadfence();
            u64 isum = *(volatile u64*)&g_isum;
            u32 imax = *(volatile u32*)&g_imax;
            float mean = (float)isum * (1.0f / 4294967296.0f) / (float)(R_N * K_N);
            float mx = __uint_as_float(imax & 0x7FFFFFFFu);   // scores >= 0
            s_th = fminf(0.05f, 0.5f * (mean + mx));
        }

        // NMS
        if (V <= 128) {
            int tot = V * V;
            if (t < TB - 32) {
                for (int p = t; p < tot; p += TB - 32) {
                    int i = p / V, j = p - i * V;
                    if (j > i) {
                        float4 bi = sbx[i], bj = sbx[j];
                        float xx1 = fmaxf(bi.x, bj.x);
                        float yy1 = fmaxf(bi.y, bj.y);
                        float xx2 = fminf(bi.z, bj.z);
                        float yy2 = fminf(bi.w, bj.w);
                        float inter = fmaxf(xx2 - xx1, 0.f) * fmaxf(yy2 - yy1, 0.f);
                        float uni = fmaxf(sarea[i] + sarea[j] - inter, 1e-9f);
                        if (inter > 0.5f * uni)
                            atomicOr(&adjw[i * 4 + (j >> 5)], 1u << (j & 31));
                    }
                }
            }
            __syncthreads();                           // B4
            if (t == 0) {        // bit-parallel closure, software-pipelined
                u64 a0 = (V >= 64) ? ~0ull : ((1ull << V) - 1ull);
                u64 a1 = (V <= 64) ? 0ull : ((V >= 128) ? ~0ull : ((1ull << (V - 64)) - 1ull));
                u64 n0 = 0, n1 = 0;
                if (V > 0) {
                    n0 = ((u64)adjw[1] << 32) | adjw[0];
                    n1 = ((u64)adjw[3] << 32) | adjw[2];
                }
                for (int i = 0; i < V; i++) {
                    u64 c0 = n0, c1 = n1;
                    if (i + 1 < V) {
                        n0 = ((u64)adjw[(i + 1) * 4 + 1] << 32) | adjw[(i + 1) * 4 + 0];
                        n1 = ((u64)adjw[(i + 1) * 4 + 3] << 32) | adjw[(i + 1) * 4 + 2];
                    }
                    u64 w = (i < 64) ? a0 : a1;
                    if ((w >> (i & 63)) & 1ull) { a0 &= ~c0; a1 &= ~c1; }
                }
                keepw[0] = (u32)a0; keepw[1] = (u32)(a0 >> 32);
                keepw[2] = (u32)a1; keepw[3] = (u32)(a1 >> 32);
            }
            __syncthreads();                           // B5
        } else {
            // generic fallback: serial block NMS (s_keep overlays dead c-arrays)
            for (int i = t; i < V; i += TB) s_keep[i] = 1;
            __syncthreads();
            for (int i = 0; i < V; i++) {
                if (s_keep[i]) {
                    float4 bi = sbx[i];
                    float  ai = sarea[i];
                    for (int j = i + 1 + t; j < V; j += TB) {
                        if (s_keep[j]) {
                            float4 bj = sbx[j];
                            float xx1 = fmaxf(bi.x, bj.x);
                            float yy1 = fmaxf(bi.y, bj.y);
                            float xx2 = fminf(bi.z, bj.z);
                            float yy2 = fminf(bi.w, bj.w);
                            float inter = fmaxf(xx2 - xx1, 0.f) * fmaxf(yy2 - yy1, 0.f);
                            float uni = fmaxf(ai + sarea[j] - inter, 1e-9f);
                            if (inter > 0.5f * uni) s_keep[j] = 0;
                        }
                    }
                }
                __syncthreads();
            }
            if (t < 32) {
                for (int s0 = 0; s0 < V; s0 += 32) {
                    int j = s0 + t;
                    u32 m = __ballot_sync(0xffffffffu, (j < V) ? s_keep[j] : 0);
                    if (t == 0) keepw[s0 >> 5] = m;
                }
            }
            __syncthreads();
        }

        if (attempt > 0) break;
        if (s_th == th_cur) break;        // speculation exact (common case)
        // rare: redo with the true threshold (reload from global)
        th_cur = s_th;
        if (t == 0) s_cnt = 0;
        __syncthreads();
        for (int r = t; r < R_N; r += TB) {
            float v = __ldg(scores + r * NCLS_P1 + b);
            if (v > th_cur) {
                int p = atomicAdd(&s_cnt, 1);
                cscore[p] = v;
                cidx[p] = r;
                float4 bx = __ldg((const float4*)boxes + r * K_N + b);
                float x1 = fminf(fmaxf(bx.x, 0.f), IMG_W_F);
                float y1 = fminf(fmaxf(bx.y, 0.f), IMG_H_F);
                float x2 = fminf(fmaxf(bx.z, 0.f), IMG_W_F);
                float y2 = fminf(fmaxf(bx.w, 0.f), IMG_H_F);
                cbx[p] = make_float4(x1, y1, x2, y2);
                carea[p] = fmaxf(x2 - x1, 0.f) * fmaxf(y2 - y1, 0.f);
            }
        }
        for (int w = t; w < 512; w += TB) adjw[w] = 0;
        __syncthreads();
    }

    // ====== emit kept (<=100) + top-byte histogram (warp 0, no barrier) ======
    if (t < 32) {
        int nk = 0;
        for (int s0 = 0; s0 < V && nk < CPC; s0 += 32) {
            u32 m = keepw[s0 >> 5];
            int kp = (m >> t) & 1;
            int myr = nk + __popc(m & ((1u << t) - 1u));
            if (kp && myr < CPC) klist[myr] = s0 + t;
            nk += __popc(m);
        }
        if (nk > CPC) nk = CPC;
        __syncwarp();
        int base = 0;
        if (t == 0) base = atomicAdd(&g_total, nk);
        base = __shfl_sync(0xffffffffu, base, 0);
        for (int k = t; k < nk; k += 32) {
            int i = klist[k];
            u32 o = ord32(sscore[i]);
            // low-32 strictly decreasing in flat (c,k) => ties break like top_k
            u64 key = ((u64)o << 32) | (u32)(((K_N - 1 - b) << 7) | (CPC - 1 - k));
            g_keys[base + k]  = key;
            g_props[base + k] = sidx[i];
            atomicAdd(&g_hist[o >> 24], 1u);
        }
    }
    __syncthreads();                                   // B6

    // ============ grid barrier 2: LAST arriver runs the tail =================
    if (t == 0) {
        __threadfence();
        int old = atomicAdd(&g_bar2, 1);
        s_last = (old == K_N - 1);
        if (s_last) {
            __threadfence();
            s_n = *(volatile int*)&g_total;
            s_scount = 0;
        }
    }
    __syncthreads();                                   // B7
    if (!s_last) return;
    int n = s_n;

    // ================= Tail: global top-100 ==================================
    u32* hist  = (u32*)(smraw + OFF_HIST);
    u64* surv  = (u64*)(smraw + OFF_SURV);
    int* sprop = (int*)(smraw + OFF_SPROP);
    u64* win   = (u64*)(smraw + OFF_WIN);
    int* wprop = (int*)(smraw + OFF_WPROP);

    if (t < 256) hist[t] = __ldcg(&g_hist[t]);
    if (t < 128) { win[t] = 0; wprop[t] = 0; }
    __syncthreads();

    u64 pref = 0;
    if (n > CPC) {
        // fast path: select top-byte bucket from the prebuilt histogram
        if (t < 32) {
            int lane = t;
            u32 h8[8]; int local = 0;
            #pragma unroll
            for (int q = 0; q < 8; q++) { h8[q] = hist[255 - 8 * lane - q]; local += (int)h8[q]; }
            int inc = local;
            #pragma unroll
            for (int o = 1; o < 32; o <<= 1) {
                int v2 = __shfl_up_sync(0xffffffffu, inc, o);
                if (lane >= o) inc += v2;
            }
            int pre = inc - local;
            if (pre < CPC && CPC <= inc) {
                int acc = pre;
                #pragma unroll
                for (int q = 0; q < 8; q++) {
                    int h = (int)h8[q];
                    if (acc + h >= CPC) {
                        s_chosen = 255 - 8 * lane - q;
                        s_spred = acc + h;
                        break;
                    }
                    acc += h;
                }
            }
        }
        __syncthreads();
        if (s_spred <= SURV_CAP) {
            pref = ((u64)(u32)s_chosen) << 56;
        } else {
            // exact fallback: full byte-radix over g_keys (rare, tie-heavy)
            u64 mask = 0;
            int need = CPC;
            int done = 0;
            pref = 0;
            #pragma unroll 1
            for (int pass = 0; pass < 8 && !done; pass++) {
                int shift = 8 * (7 - pass);
                if (t < 256) hist[t] = 0;
                __syncthreads();
                for (int i = t; i < n; i += TB) {
                    u64 kk = __ldcg(&g_keys[i]);
                    if ((kk & mask) == pref)
                        atomicAdd(&hist[(u32)(kk >> shift) & 255u], 1u);
                }
                __syncthreads();
                if (t < 32) {
                    int lane = t;
                    u32 h8[8]; int local = 0;
                    #pragma unroll
                    for (int q = 0; q < 8; q++) { h8[q] = hist[255 - 8 * lane - q]; local += (int)h8[q]; }
                    int inc = local;
                    #pragma unroll
                    for (int o = 1; o < 32; o <<= 1) {
                        int v2 = __shfl_up_sync(0xffffffffu, inc, o);
                        if (lane >= o) inc += v2;
                    }
                    int pre = inc - local;
                    if (pre < need && need <= inc) {
                        int acc = pre;
                        #pragma unroll
                        for (int q = 0; q < 8; q++) {
                            int h = (int)h8[q];
                            if (acc + h >= need) { s_chosen = 255 - 8 * lane - q; s_need = need - acc; break; }
                            acc += h;
                        }
                    }
                }
                __syncthreads();
                if (t == 0) s_spred = (CPC - s_need) + (int)hist[s_chosen];
                pref |= ((u64)(u32)s_chosen) << shift;
                mask |= 255ull << shift;
                need = s_need;
                __syncthreads();
                if (s_spred <= SURV_CAP) done = 1;
            }
        }
    }

    // gather survivors (key >= pref; pref==0 when n<=CPC => all)
    for (int i = t; i < n; i += TB) {
        u64 kk = __ldcg(&g_keys[i]);
        if (kk >= pref) {
            int p = atomicAdd(&s_scount, 1);
            if (p < SURV_CAP) { surv[p] = kk; sprop[p] = __ldcg(&g_props[i]); }
        }
    }
    __syncthreads();
    int S = s_scount;
    if (S > SURV_CAP) S = SURV_CAP;

    // rank survivors by full key (unique); keep top 100
    if (t < S) {
        u64 kk = surv[t];
        int r = 0;
        for (int j = 0; j < S; j++) r += (surv[j] > kk);
        if (r < CPC) { win[r] = kk; wprop[r] = sprop[t]; }
    }
    __syncthreads();

    // ---- Output: [100, 87] = box(4) | score | class | full_scores(81) ----
    for (int e = t; e < CPC * OUT_COLS; e += TB) {
        int row = e / OUT_COLS;
        int col = e - row * OUT_COLS;
        u64 key = win[row];
        u32 o = (u32)(key >> 32);
        float val = 0.f;
        if (o != 0u) {
            int c = (K_N - 1) - (int)(((u32)key >> 7) & 127u);
            int prop = wprop[row];
            if (col < 4) {
                float bv = __ldg(boxes + prop * (K_N * 4) + c * 4 + col);
                float lim = (col & 1) ? IMG_H_F : IMG_W_F;
                val = fminf(fmaxf(bv, 0.f), lim);
            } else if (col == 4) {
                val = __uint_as_float(o & 0x7FFFFFFFu);
            } else if (col == 5) {
                val = (float)c;
            } else {
                val = __ldg(scores + prop * NCLS_P1 + (col - 6));
            }
        }
        out[e] = val;
    }
    __syncthreads();
    // reset globals for next graph replay
    if (t < 256) g_hist[t] = 0;
    if (t == 0) {
        g_bar1 = 0; g_bar2 = 0; g_total = 0;
        g_isum = 0; g_imax = 0;
    }
}

// ---------------------------------------------------------------------------
extern "C" void kernel_launch(void* const* d_in, const int* in_sizes, int n_in,
                              void* d_out, int out_size) {
    const float* boxes  = (const float*)d_in[0];
    const float* scores = (const float*)d_in[1];
    if (in_sizes[0] != R_N * K_N * 4) {
        boxes  = (const float*)d_in[1];
        scores = (const float*)d_in[0];
    }
    cudaFuncSetAttribute(fused_kernel, cudaFuncAttributeMaxDynamicSharedMemorySize, DYN_SMEM);
    fused_kernel<<<K_N, TB, DYN_SMEM>>>(boxes, scores, (float*)d_out);
}